// round 12
// baseline (speedup 1.0000x reference)
#include <cuda_runtime.h>
#include <cuda_fp16.h>
#include <math.h>
#include <stdint.h>

// ---------------------------------------------------------------------------
// ContinuousFilterConv, mma.sync fp16 single-pass, pair-pipelined, 16 warps.
//   C[e,i] = sum_u h[e,u] * P_u[e,i],  P_u = t @ W2'_u  (u=128 row: W2'=b2, h=1)
//   t, W2 fp16 (rel err ~3e-4); h applied in fp32 per u.
//   Two u per stage share A (t) fragments; B 4-slab cp.async ring.
//   512 threads, warp tile 32Mx32N -> ~145 regs, no spills, occ 25%.
// ---------------------------------------------------------------------------

#define N_NODES 20000
#define N_EDGES 8192
#define UNITS   128
#define NGAUSS  50
#define LDA     136            // padded row (fp16 elems) = 272 B

// ---- gmem scratch (static only) ----
__device__ __align__(16) float  g_hT[129 * N_EDGES];     // hT[u][e], row 128 == 1
__device__ __align__(16) __half g_th[N_EDGES * LDA];     // t fp16, padded rows
__device__ uint4 g_B4[129 * 2176];                       // W2'_u fp16, padded rows
__device__ __align__(16) float g_msg[N_NODES * UNITS];

// ---- helpers ----
__device__ __forceinline__ uint32_t smem_u32(const void* p) {
    uint32_t a;
    asm("{ .reg .u64 t; cvta.to.shared.u64 t, %1; cvt.u32.u64 %0, t; }" : "=r"(a) : "l"(p));
    return a;
}
__device__ __forceinline__ void cp16(uint32_t saddr, const void* g) {
    asm volatile("cp.async.cg.shared.global [%0], [%1], 16;" :: "r"(saddr), "l"(g) : "memory");
}
#define CP_COMMIT() asm volatile("cp.async.commit_group;" ::: "memory")
#define CP_WAIT0()  asm volatile("cp.async.wait_group 0;" ::: "memory")

#define LDSM4(R, A) \
    asm volatile("ldmatrix.sync.aligned.m8n8.x4.shared.b16 {%0,%1,%2,%3}, [%4];" \
        : "=r"((R)[0]), "=r"((R)[1]), "=r"((R)[2]), "=r"((R)[3]) : "r"(A))

#define MMA(C, A, B0, B1) \
    asm volatile("mma.sync.aligned.m16n8k16.row.col.f32.f16.f16.f32 " \
        "{%0,%1,%2,%3},{%4,%5,%6,%7},{%8,%9},{%0,%1,%2,%3};" \
        : "+f"((C)[0]), "+f"((C)[1]), "+f"((C)[2]), "+f"((C)[3]) \
        : "r"((A)[0]), "r"((A)[1]), "r"((A)[2]), "r"((A)[3]), "r"(B0), "r"(B1))

__device__ __forceinline__ uint32_t pack_h2(float x0, float x1) {
    return (uint32_t)__half_as_ushort(__float2half(x0))
         | ((uint32_t)__half_as_ushort(__float2half(x1)) << 16);
}
__device__ __forceinline__ float silu_f(float x) { return x / (1.0f + expf(-x)); }

// ---------------------------------------------------------------------------
// kernel 1: W2/b2 -> fp16 padded rows + grid-stride zero of g_msg (fused)
// ---------------------------------------------------------------------------
__global__ __launch_bounds__(256) void w2_zero_kernel(
    const float* __restrict__ W2, const float* __restrict__ b2)
{
    int g  = blockIdx.x * 256 + threadIdx.x;       // < 129*2048
    int u  = g >> 11, rem = g & 2047;
    int i  = rem >> 4, jq = rem & 15;
    const float* row = (u < 128) ? (W2 + (long long)u * 16384) : b2;
    float4 a = *(const float4*)(row + i * 128 + jq * 8);
    float4 b = *(const float4*)(row + i * 128 + jq * 8 + 4);
    uint4 o;
    o.x = pack_h2(a.x, a.y);
    o.y = pack_h2(a.z, a.w);
    o.z = pack_h2(b.x, b.y);
    o.w = pack_h2(b.z, b.w);
    g_B4[u * 2176 + i * 17 + jq] = o;
    for (int k = g; k < N_NODES * UNITS / 4; k += 1032 * 256)
        ((float4*)g_msg)[k] = make_float4(0.f, 0.f, 0.f, 0.f);
}

// ---------------------------------------------------------------------------
// kernel 2: per-edge h (gaussian -> dense -> silu, transposed) + t (gather @ Wt)
// ---------------------------------------------------------------------------
__global__ __launch_bounds__(256) void prep_kernel(
    const float* __restrict__ nf, const int* __restrict__ eidx,
    const float* __restrict__ dist, const float* __restrict__ W1,
    const float* __restrict__ b1, const float* __restrict__ Wt)
{
    extern __shared__ float sm[];
    float* Wt_s = sm;                       // 16384
    float* W1_s = Wt_s + 16384;             // 6400
    float* b1_s = W1_s + 6400;              // 128
    float* X_s  = b1_s + 128;               // 64*129
    float* df_s = X_s + 64 * 129;           // 64*51
    const int tid = threadIdx.x;
    const int e0  = blockIdx.x * 64;

    for (int idx = tid; idx < 16384; idx += 256) Wt_s[idx] = Wt[idx];
    for (int idx = tid; idx < NGAUSS * UNITS; idx += 256) W1_s[idx] = W1[idx];
    if (tid < 128) b1_s[tid] = b1[tid];
    for (int idx = tid; idx < 64 * NGAUSS; idx += 256) {
        int e = idx & 63, g = idx >> 6;
        float d = dist[e0 + e];
        float c = (30.0f / 49.0f) * (float)g;
        float x = d - c;
        df_s[e * 51 + g] = expf(-10.0f * x * x);
    }
    for (int idx = tid; idx < 64 * UNITS; idx += 256) {
        int e = idx >> 7, j = idx & 127;
        int s = eidx[e0 + e];
        X_s[e * 129 + j] = nf[(long long)s * UNITS + j];
    }
    __syncthreads();

    for (int o = tid; o < 64 * UNITS; o += 256) {
        int u = o >> 6, e = o & 63;
        float acc = b1_s[u];
        const float* dfr = df_s + e * 51;
#pragma unroll
        for (int g = 0; g < NGAUSS; ++g) acc += dfr[g] * W1_s[g * UNITS + u];
        g_hT[u * N_EDGES + e0 + e] = silu_f(acc);
    }
    for (int idx = tid; idx < 64; idx += 256)
        g_hT[128 * N_EDGES + e0 + idx] = 1.0f;

    for (int o = tid; o < 64 * UNITS; o += 256) {
        int e = o >> 7, u = o & 127;
        float acc = 0.0f;
        const float* xr = X_s + e * 129;
#pragma unroll
        for (int j = 0; j < UNITS; ++j) acc += xr[j] * Wt_s[j * UNITS + u];
        g_th[(e0 + e) * LDA + u] = __float2half(acc);
    }
}

// ---------------------------------------------------------------------------
// kernel 3: main GEMM, pair-pipelined, 512 threads (16 warps, 4Mx4N of 32x32).
// ---------------------------------------------------------------------------
#define TH_OFF 0
#define HS_OFF 34816
#define B_OFF  68096
#define BBUF   34816
#define CONV_SMEM 207360   // 68096 + 4*34816

__global__ __launch_bounds__(512, 1) void conv_kernel(
    const int* __restrict__ eidx, const float* __restrict__ dist)
{
    extern __shared__ char smem[];
    const uint32_t sb = smem_u32(smem);
    const int tid = threadIdx.x, l = tid & 31, wid = tid >> 5;
    const int e0 = blockIdx.x * 128;
    const int ub = blockIdx.y ? 65 : 0;
    const int ue = blockIdx.y ? 129 : 65;
    const int nu = ue - ub;                 // 65 or 64
    const int np = nu >> 1;
    const int tail = nu & 1;

    // prologue group: B[ub], B[ub+1] -> slabs 0,1; th tile; h slice
    {
        const uint4* gb = g_B4 + ub * 2176;
        for (int k = tid; k < 2 * 2176; k += 512) cp16(sb + B_OFF + k * 16, gb + k);
        const uint4* gt = (const uint4*)(g_th + (long long)e0 * LDA);
        for (int k = tid; k < 2176; k += 512) cp16(sb + TH_OFF + k * 16, gt + k);
        for (int k = tid; k < nu * 32; k += 512) {
            int u_l = k >> 5, off = k & 31;
            cp16(sb + HS_OFF + k * 16,
                 (const uint4*)(g_hT + (ub + u_l) * N_EDGES + e0) + off);
        }
        CP_COMMIT();
    }

    const int m0w = (wid & 3) * 32;         // 4 M groups of 32
    const int n0w = (wid >> 2) * 32;        // 4 N groups of 32
    const uint32_t aOff = (uint32_t)(m0w + (l & 15)) * (LDA * 2)
                        + (uint32_t)(l >> 4) * 16;
    const uint32_t bOff = (uint32_t)(n0w + (l & 7) + ((l >> 4) & 1) * 8) * (LDA * 2)
                        + (uint32_t)((l >> 3) & 1) * 16;
    const float* hbase = (const float*)(smem + HS_OFF);

    float accC[2][4][4];
#pragma unroll
    for (int mt = 0; mt < 2; ++mt)
#pragma unroll
        for (int nt = 0; nt < 4; ++nt)
#pragma unroll
            for (int q = 0; q < 4; ++q) accC[mt][nt][q] = 0.0f;

    for (int p = 0; p < np; ++p) {
        const int k0 = 2 * p;
        CP_WAIT0();
        __syncthreads();

        // prefetch pair p+1 into slabs ((k0+2)&3, (k0+3)&3); one commit per iter
        {
            int ka = k0 + 2, kb = k0 + 3;
            if (ka < nu) {
                const uint4* gb = g_B4 + (ub + ka) * 2176;
                uint32_t dst = sb + B_OFF + (uint32_t)(ka & 3) * BBUF;
                for (int kk = tid; kk < 2176; kk += 512) cp16(dst + kk * 16, gb + kk);
            }
            if (kb < nu) {
                const uint4* gb = g_B4 + (ub + kb) * 2176;
                uint32_t dst = sb + B_OFF + (uint32_t)(kb & 3) * BBUF;
                for (int kk = tid; kk < 2176; kk += 512) cp16(dst + kk * 16, gb + kk);
            }
            CP_COMMIT();
        }

        const uint32_t b0Base = sb + B_OFF + (uint32_t)(k0 & 3) * BBUF + bOff;
        const uint32_t b1Base = sb + B_OFF + (uint32_t)((k0 + 1) & 3) * BBUF + bOff;

        float accP0[2][4][4], accP1[2][4][4];
#pragma unroll
        for (int mt = 0; mt < 2; ++mt)
#pragma unroll
            for (int nt = 0; nt < 4; ++nt)
#pragma unroll
                for (int q = 0; q < 4; ++q) { accP0[mt][nt][q] = 0.0f; accP1[mt][nt][q] = 0.0f; }

#pragma unroll
        for (int kc = 0; kc < 8; ++kc) {
            uint32_t af[2][4], bf0[2][4], bf1[2][4];
#pragma unroll
            for (int mt = 0; mt < 2; ++mt)
                LDSM4(af[mt], sb + TH_OFF + aOff
                              + (uint32_t)mt * 16 * (LDA * 2) + (uint32_t)kc * 32);
#pragma unroll
            for (int bt = 0; bt < 2; ++bt) {
                LDSM4(bf0[bt], b0Base + (uint32_t)bt * 16 * (LDA * 2) + (uint32_t)kc * 32);
                LDSM4(bf1[bt], b1Base + (uint32_t)bt * 16 * (LDA * 2) + (uint32_t)kc * 32);
            }
#pragma unroll
            for (int mt = 0; mt < 2; ++mt)
#pragma unroll
                for (int nt = 0; nt < 4; ++nt) {
                    MMA(accP0[mt][nt], af[mt],
                        bf0[nt >> 1][(nt & 1) * 2], bf0[nt >> 1][(nt & 1) * 2 + 1]);
                    MMA(accP1[mt][nt], af[mt],
                        bf1[nt >> 1][(nt & 1) * 2], bf1[nt >> 1][(nt & 1) * 2 + 1]);
                }
        }

        const float* hrow0 = hbase + k0 * 128;
        const float* hrow1 = hrow0 + 128;
#pragma unroll
        for (int mt = 0; mt < 2; ++mt) {
            int r = m0w + mt * 16 + (l >> 2);
            float h01 = hrow0[r], h02 = hrow0[r + 8];
            float h11 = hrow1[r], h12 = hrow1[r + 8];
#pragma unroll
            for (int nt = 0; nt < 4; ++nt) {
                accC[mt][nt][0] += h01 * accP0[mt][nt][0] + h11 * accP1[mt][nt][0];
                accC[mt][nt][1] += h01 * accP0[mt][nt][1] + h11 * accP1[mt][nt][1];
                accC[mt][nt][2] += h02 * accP0[mt][nt][2] + h12 * accP1[mt][nt][2];
                accC[mt][nt][3] += h02 * accP0[mt][nt][3] + h12 * accP1[mt][nt][3];
            }
        }
    }

    if (tail) {            // last odd u (k = nu-1)
        const int k0 = nu - 1;
        CP_WAIT0();
        __syncthreads();
        const uint32_t b0Base = sb + B_OFF + (uint32_t)(k0 & 3) * BBUF + bOff;

        float accP0[2][4][4];
#pragma unroll
        for (int mt = 0; mt < 2; ++mt)
#pragma unroll
            for (int nt = 0; nt < 4; ++nt)
#pragma unroll
                for (int q = 0; q < 4; ++q) accP0[mt][nt][q] = 0.0f;

#pragma unroll
        for (int kc = 0; kc < 8; ++kc) {
            uint32_t af[2][4], bf0[2][4];
#pragma unroll
            for (int mt = 0; mt < 2; ++mt)
                LDSM4(af[mt], sb + TH_OFF + aOff
                              + (uint32_t)mt * 16 * (LDA * 2) + (uint32_t)kc * 32);
#pragma unroll
            for (int bt = 0; bt < 2; ++bt)
                LDSM4(bf0[bt], b0Base + (uint32_t)bt * 16 * (LDA * 2) + (uint32_t)kc * 32);
#pragma unroll
            for (int mt = 0; mt < 2; ++mt)
#pragma unroll
                for (int nt = 0; nt < 4; ++nt)
                    MMA(accP0[mt][nt], af[mt],
                        bf0[nt >> 1][(nt & 1) * 2], bf0[nt >> 1][(nt & 1) * 2 + 1]);
        }
        const float* hrow0 = hbase + k0 * 128;
#pragma unroll
        for (int mt = 0; mt < 2; ++mt) {
            int r = m0w + mt * 16 + (l >> 2);
            float h01 = hrow0[r], h02 = hrow0[r + 8];
#pragma unroll
            for (int nt = 0; nt < 4; ++nt) {
                accC[mt][nt][0] += h01 * accP0[mt][nt][0];
                accC[mt][nt][1] += h01 * accP0[mt][nt][1];
                accC[mt][nt][2] += h02 * accP0[mt][nt][2];
                accC[mt][nt][3] += h02 * accP0[mt][nt][3];
            }
        }
    }

    // epilogue: cutoff mask + scatter-add
#pragma unroll
    for (int mt = 0; mt < 2; ++mt) {
        int e1 = e0 + m0w + mt * 16 + (l >> 2);
        int e2 = e1 + 8;
        float d1 = dist[e1], d2 = dist[e2];
        bool ok1 = (d1 <= 8.0f), ok2 = (d2 <= 8.0f);
        float* r1 = g_msg + (long long)eidx[N_EDGES + e1] * UNITS;
        float* r2 = g_msg + (long long)eidx[N_EDGES + e2] * UNITS;
#pragma unroll
        for (int nt = 0; nt < 4; ++nt) {
            int n = n0w + nt * 8 + (l & 3) * 2;
            if (ok1) {
                atomicAdd(r1 + n,     accC[mt][nt][0]);
                atomicAdd(r1 + n + 1, accC[mt][nt][1]);
            }
            if (ok2) {
                atomicAdd(r2 + n,     accC[mt][nt][2]);
                atomicAdd(r2 + n + 1, accC[mt][nt][3]);
            }
        }
    }
}

// ---------------------------------------------------------------------------
// kernel 4: out = silu(messages), float4
// ---------------------------------------------------------------------------
__global__ void out_kernel(float* __restrict__ out) {
    int i = blockIdx.x * blockDim.x + threadIdx.x;  // grid sized exactly (160000)
    float4 x = ((const float4*)g_msg)[i];
    float4 y;
    y.x = silu_f(x.x); y.y = silu_f(x.y); y.z = silu_f(x.z); y.w = silu_f(x.w);
    ((float4*)out)[i] = y;
}

// ---------------------------------------------------------------------------
extern "C" void kernel_launch(void* const* d_in, const int* in_sizes, int n_in,
                              void* d_out, int out_size) {
    const float* nf   = (const float*)d_in[0];
    const int*   eidx = (const int*)  d_in[1];
    const float* dist = (const float*)d_in[2];
    const float* W1   = (const float*)d_in[3];
    const float* b1   = (const float*)d_in[4];
    const float* W2   = (const float*)d_in[5];
    const float* b2   = (const float*)d_in[6];
    const float* Wt   = (const float*)d_in[7];
    float* out = (float*)d_out;

    const int PREP_SMEM = (16384 + 6400 + 128 + 64 * 129 + 64 * 51) * 4;
    cudaFuncSetAttribute(prep_kernel, cudaFuncAttributeMaxDynamicSharedMemorySize, PREP_SMEM);
    cudaFuncSetAttribute(conv_kernel, cudaFuncAttributeMaxDynamicSharedMemorySize, CONV_SMEM);

    w2_zero_kernel<<<129 * 2048 / 256, 256>>>(W2, b2);
    prep_kernel<<<N_EDGES / 64, 256, PREP_SMEM>>>(nf, eidx, dist, W1, b1, Wt);
    conv_kernel<<<dim3(N_EDGES / 128, 2), 512, CONV_SMEM>>>(eidx, dist);
    out_kernel<<<(N_NODES * UNITS / 4) / 256, 256>>>(out);
}

// round 13
// speedup vs baseline: 1.0493x; 1.0493x over previous
#include <cuda_runtime.h>
#include <cuda_fp16.h>
#include <math.h>
#include <stdint.h>

// ---------------------------------------------------------------------------
// ContinuousFilterConv, mma.sync fp16, persistent-A registers, h folded in fp16.
//   C[e,i] = sum_u h[e,u] * (t @ W2'_u)[e,i]   (u=128 row: W2'=b2, h=1)
//   t fragments live in registers for all u; per u: a_s = h*t (fp16), then
//   MMA accumulates directly into fp32 accC. B 4-slab cp.async ring.
//   256 threads, 8 warps 4(M)x2(N), warp tile 32Mx64N -> ~180 regs, no spills.
// ---------------------------------------------------------------------------

#define N_NODES 20000
#define N_EDGES 8192
#define UNITS   128
#define NGAUSS  50
#define LDA     136            // padded row (fp16 elems) = 272 B

// ---- gmem scratch (static only) ----
__device__ __align__(16) float  g_hT[129 * N_EDGES];     // hT[u][e], row 128 == 1
__device__ __align__(16) __half g_th[N_EDGES * LDA];     // t fp16, padded rows
__device__ uint4 g_B4[129 * 2176];                       // W2'_u fp16, padded rows
__device__ __align__(16) float g_msg[N_NODES * UNITS];

// ---- helpers ----
__device__ __forceinline__ uint32_t smem_u32(const void* p) {
    uint32_t a;
    asm("{ .reg .u64 t; cvta.to.shared.u64 t, %1; cvt.u32.u64 %0, t; }" : "=r"(a) : "l"(p));
    return a;
}
__device__ __forceinline__ void cp16(uint32_t saddr, const void* g) {
    asm volatile("cp.async.cg.shared.global [%0], [%1], 16;" :: "r"(saddr), "l"(g) : "memory");
}
#define CP_COMMIT() asm volatile("cp.async.commit_group;" ::: "memory")
#define CP_WAIT1()  asm volatile("cp.async.wait_group 1;" ::: "memory")
#define CP_WAIT2()  asm volatile("cp.async.wait_group 2;" ::: "memory")

#define LDSM4(R, A) \
    asm volatile("ldmatrix.sync.aligned.m8n8.x4.shared.b16 {%0,%1,%2,%3}, [%4];" \
        : "=r"((R)[0]), "=r"((R)[1]), "=r"((R)[2]), "=r"((R)[3]) : "r"(A))

#define MMA(C, A0, A1, A2, A3, B0, B1) \
    asm volatile("mma.sync.aligned.m16n8k16.row.col.f32.f16.f16.f32 " \
        "{%0,%1,%2,%3},{%4,%5,%6,%7},{%8,%9},{%0,%1,%2,%3};" \
        : "+f"((C)[0]), "+f"((C)[1]), "+f"((C)[2]), "+f"((C)[3]) \
        : "r"(A0), "r"(A1), "r"(A2), "r"(A3), "r"(B0), "r"(B1))

__device__ __forceinline__ uint32_t mulh2(uint32_t a, uint32_t h) {
    uint32_t r;
    asm("mul.rn.f16x2 %0, %1, %2;" : "=r"(r) : "r"(a), "r"(h));
    return r;
}
__device__ __forceinline__ uint32_t h2dup(float x) {
    uint32_t r;
    asm("{ .reg .f16 h; cvt.rn.f16.f32 h, %1; mov.b32 %0, {h, h}; }" : "=r"(r) : "f"(x));
    return r;
}
__device__ __forceinline__ uint32_t pack_h2(float x0, float x1) {
    return (uint32_t)__half_as_ushort(__float2half(x0))
         | ((uint32_t)__half_as_ushort(__float2half(x1)) << 16);
}
__device__ __forceinline__ float silu_f(float x) { return x / (1.0f + expf(-x)); }

// ---------------------------------------------------------------------------
// kernel 1: W2/b2 -> fp16 padded rows + grid-stride zero of g_msg (fused)
// ---------------------------------------------------------------------------
__global__ __launch_bounds__(256) void w2_zero_kernel(
    const float* __restrict__ W2, const float* __restrict__ b2)
{
    int g  = blockIdx.x * 256 + threadIdx.x;       // < 129*2048
    int u  = g >> 11, rem = g & 2047;
    int i  = rem >> 4, jq = rem & 15;
    const float* row = (u < 128) ? (W2 + (long long)u * 16384) : b2;
    float4 a = *(const float4*)(row + i * 128 + jq * 8);
    float4 b = *(const float4*)(row + i * 128 + jq * 8 + 4);
    uint4 o;
    o.x = pack_h2(a.x, a.y);
    o.y = pack_h2(a.z, a.w);
    o.z = pack_h2(b.x, b.y);
    o.w = pack_h2(b.z, b.w);
    g_B4[u * 2176 + i * 17 + jq] = o;
    for (int k = g; k < N_NODES * UNITS / 4; k += 1032 * 256)
        ((float4*)g_msg)[k] = make_float4(0.f, 0.f, 0.f, 0.f);
}

// ---------------------------------------------------------------------------
// kernel 2: per-edge h (gaussian -> dense -> silu, transposed) + t (gather @ Wt)
// ---------------------------------------------------------------------------
__global__ __launch_bounds__(256) void prep_kernel(
    const float* __restrict__ nf, const int* __restrict__ eidx,
    const float* __restrict__ dist, const float* __restrict__ W1,
    const float* __restrict__ b1, const float* __restrict__ Wt)
{
    extern __shared__ float sm[];
    float* Wt_s = sm;                       // 16384
    float* W1_s = Wt_s + 16384;             // 6400
    float* b1_s = W1_s + 6400;              // 128
    float* X_s  = b1_s + 128;               // 64*129
    float* df_s = X_s + 64 * 129;           // 64*51
    const int tid = threadIdx.x;
    const int e0  = blockIdx.x * 64;

    for (int idx = tid; idx < 16384; idx += 256) Wt_s[idx] = Wt[idx];
    for (int idx = tid; idx < NGAUSS * UNITS; idx += 256) W1_s[idx] = W1[idx];
    if (tid < 128) b1_s[tid] = b1[tid];
    for (int idx = tid; idx < 64 * NGAUSS; idx += 256) {
        int e = idx & 63, g = idx >> 6;
        float d = dist[e0 + e];
        float c = (30.0f / 49.0f) * (float)g;
        float x = d - c;
        df_s[e * 51 + g] = expf(-10.0f * x * x);
    }
    for (int idx = tid; idx < 64 * UNITS; idx += 256) {
        int e = idx >> 7, j = idx & 127;
        int s = eidx[e0 + e];
        X_s[e * 129 + j] = nf[(long long)s * UNITS + j];
    }
    __syncthreads();

    for (int o = tid; o < 64 * UNITS; o += 256) {
        int u = o >> 6, e = o & 63;
        float acc = b1_s[u];
        const float* dfr = df_s + e * 51;
#pragma unroll
        for (int g = 0; g < NGAUSS; ++g) acc += dfr[g] * W1_s[g * UNITS + u];
        g_hT[u * N_EDGES + e0 + e] = silu_f(acc);
    }
    for (int idx = tid; idx < 64; idx += 256)
        g_hT[128 * N_EDGES + e0 + idx] = 1.0f;

    for (int o = tid; o < 64 * UNITS; o += 256) {
        int e = o >> 7, u = o & 127;
        float acc = 0.0f;
        const float* xr = X_s + e * 129;
#pragma unroll
        for (int j = 0; j < UNITS; ++j) acc += xr[j] * Wt_s[j * UNITS + u];
        g_th[(e0 + e) * LDA + u] = __float2half(acc);
    }
}

// ---------------------------------------------------------------------------
// kernel 3: main GEMM, persistent-A, 256 threads (8 warps, 4Mx2N of 32x64).
// ---------------------------------------------------------------------------
#define HS_OFF 0
#define B_OFF  33280
#define BBUF   34816
#define CONV_SMEM 172544   // 33280 + 4*34816

__global__ __launch_bounds__(256, 1) void conv_kernel(
    const int* __restrict__ eidx, const float* __restrict__ dist)
{
    extern __shared__ char smem[];
    const uint32_t sb = smem_u32(smem);
    const int tid = threadIdx.x, l = tid & 31, wid = tid >> 5;
    const int e0 = blockIdx.x * 128;
    const int ub = blockIdx.y ? 65 : 0;
    const int ue = blockIdx.y ? 129 : 65;
    const int nu = ue - ub;                 // 65 or 64

    // G0: B[ub] -> slab0, t tile -> slab3 (staging), h slice -> HS
    {
        const uint4* gb = g_B4 + ub * 2176;
        for (int k = tid; k < 2176; k += 256) cp16(sb + B_OFF + k * 16, gb + k);
        const uint4* gt = (const uint4*)(g_th + (long long)e0 * LDA);
        for (int k = tid; k < 2176; k += 256)
            cp16(sb + B_OFF + 3 * BBUF + k * 16, gt + k);
        for (int k = tid; k < nu * 32; k += 256) {
            int u_l = k >> 5, off = k & 31;
            cp16(sb + HS_OFF + k * 16,
                 (const uint4*)(g_hT + (ub + u_l) * N_EDGES + e0) + off);
        }
        CP_COMMIT();
    }
    // G1: B[ub+1] -> slab1
    {
        const uint4* gb = g_B4 + (ub + 1) * 2176;
        for (int k = tid; k < 2176; k += 256) cp16(sb + B_OFF + BBUF + k * 16, gb + k);
        CP_COMMIT();
    }

    const int m0w = (wid & 3) * 32;         // 4 M groups of 32 rows
    const int n0w = (wid >> 2) * 64;        // 2 N groups of 64 cols
    const uint32_t aOff = (uint32_t)(m0w + (l & 7) + ((l >> 3) & 1) * 8) * (LDA * 2)
                        + (uint32_t)(l >> 4) * 16;
    const uint32_t bOff = (uint32_t)(n0w + (l & 7) + ((l >> 4) & 1) * 8) * (LDA * 2)
                        + (uint32_t)((l >> 3) & 1) * 16;
    const float* hbase = (const float*)(smem + HS_OFF);
    const int hr = (l >> 2);                // fragment row within 16-tile

    CP_WAIT1();            // G0 done: t, h, B0 ready
    __syncthreads();

    // load persistent A fragments from t staging (slab 3)
    uint32_t ap[2][8][4];
#pragma unroll
    for (int mt = 0; mt < 2; ++mt)
#pragma unroll
        for (int kc = 0; kc < 8; ++kc)
            LDSM4(ap[mt][kc], sb + B_OFF + 3 * BBUF + aOff
                              + (uint32_t)mt * 16 * (LDA * 2) + (uint32_t)kc * 32);
    __syncthreads();       // slab 3 free for the ring

    float accC[2][8][4];
#pragma unroll
    for (int mt = 0; mt < 2; ++mt)
#pragma unroll
        for (int nt = 0; nt < 8; ++nt)
#pragma unroll
            for (int q = 0; q < 4; ++q) accC[mt][nt][q] = 0.0f;

    for (int k = 0; k < nu; ++k) {
        // prefetch B[k+2] into slab (k+2)&3; exactly one commit per iter
        if (k + 2 < nu) {
            const uint4* gb = g_B4 + (ub + k + 2) * 2176;
            uint32_t dst = sb + B_OFF + (uint32_t)((k + 2) & 3) * BBUF;
            for (int kk = tid; kk < 2176; kk += 256) cp16(dst + kk * 16, gb + kk);
        }
        CP_COMMIT();
        CP_WAIT2();        // B[k] (group k) complete
        __syncthreads();

        // per-u h scale factors (fp16x2 duplicated)
        const float* hrow = hbase + k * 128;
        uint32_t h00 = h2dup(hrow[m0w + hr]);
        uint32_t h01 = h2dup(hrow[m0w + hr + 8]);
        uint32_t h10 = h2dup(hrow[m0w + 16 + hr]);
        uint32_t h11 = h2dup(hrow[m0w + 16 + hr + 8]);

        const uint32_t bBase = sb + B_OFF + (uint32_t)(k & 3) * BBUF + bOff;

#pragma unroll
        for (int kc = 0; kc < 8; ++kc) {
            uint32_t bf[4][4];
#pragma unroll
            for (int bt = 0; bt < 4; ++bt)
                LDSM4(bf[bt], bBase + (uint32_t)bt * 16 * (LDA * 2) + (uint32_t)kc * 32);

            uint32_t as0[4], as1[4];
            as0[0] = mulh2(ap[0][kc][0], h00);
            as0[1] = mulh2(ap[0][kc][1], h01);
            as0[2] = mulh2(ap[0][kc][2], h00);
            as0[3] = mulh2(ap[0][kc][3], h01);
            as1[0] = mulh2(ap[1][kc][0], h10);
            as1[1] = mulh2(ap[1][kc][1], h11);
            as1[2] = mulh2(ap[1][kc][2], h10);
            as1[3] = mulh2(ap[1][kc][3], h11);

#pragma unroll
            for (int nt = 0; nt < 8; ++nt) {
                uint32_t b0 = bf[nt >> 1][(nt & 1) * 2];
                uint32_t b1 = bf[nt >> 1][(nt & 1) * 2 + 1];
                MMA(accC[0][nt], as0[0], as0[1], as0[2], as0[3], b0, b1);
                MMA(accC[1][nt], as1[0], as1[1], as1[2], as1[3], b0, b1);
            }
        }
    }

    // epilogue: cutoff mask + scatter-add
#pragma unroll
    for (int mt = 0; mt < 2; ++mt) {
        int e1 = e0 + m0w + mt * 16 + hr;
        int e2 = e1 + 8;
        float d1 = dist[e1], d2 = dist[e2];
        bool ok1 = (d1 <= 8.0f), ok2 = (d2 <= 8.0f);
        float* r1 = g_msg + (long long)eidx[N_EDGES + e1] * UNITS;
        float* r2 = g_msg + (long long)eidx[N_EDGES + e2] * UNITS;
#pragma unroll
        for (int nt = 0; nt < 8; ++nt) {
            int n = n0w + nt * 8 + (l & 3) * 2;
            if (ok1) {
                atomicAdd(r1 + n,     accC[mt][nt][0]);
                atomicAdd(r1 + n + 1, accC[mt][nt][1]);
            }
            if (ok2) {
                atomicAdd(r2 + n,     accC[mt][nt][2]);
                atomicAdd(r2 + n + 1, accC[mt][nt][3]);
            }
        }
    }
}

// ---------------------------------------------------------------------------
// kernel 4: out = silu(messages), float4
// ---------------------------------------------------------------------------
__global__ void out_kernel(float* __restrict__ out) {
    int i = blockIdx.x * blockDim.x + threadIdx.x;  // grid sized exactly (160000)
    float4 x = ((const float4*)g_msg)[i];
    float4 y;
    y.x = silu_f(x.x); y.y = silu_f(x.y); y.z = silu_f(x.z); y.w = silu_f(x.w);
    ((float4*)out)[i] = y;
}

// ---------------------------------------------------------------------------
extern "C" void kernel_launch(void* const* d_in, const int* in_sizes, int n_in,
                              void* d_out, int out_size) {
    const float* nf   = (const float*)d_in[0];
    const int*   eidx = (const int*)  d_in[1];
    const float* dist = (const float*)d_in[2];
    const float* W1   = (const float*)d_in[3];
    const float* b1   = (const float*)d_in[4];
    const float* W2   = (const float*)d_in[5];
    const float* b2   = (const float*)d_in[6];
    const float* Wt   = (const float*)d_in[7];
    float* out = (float*)d_out;

    const int PREP_SMEM = (16384 + 6400 + 128 + 64 * 129 + 64 * 51) * 4;
    cudaFuncSetAttribute(prep_kernel, cudaFuncAttributeMaxDynamicSharedMemorySize, PREP_SMEM);
    cudaFuncSetAttribute(conv_kernel, cudaFuncAttributeMaxDynamicSharedMemorySize, CONV_SMEM);

    w2_zero_kernel<<<129 * 2048 / 256, 256>>>(W2, b2);
    prep_kernel<<<N_EDGES / 64, 256, PREP_SMEM>>>(nf, eidx, dist, W1, b1, Wt);
    conv_kernel<<<dim3(N_EDGES / 128, 2), 256, CONV_SMEM>>>(eidx, dist);
    out_kernel<<<(N_NODES * UNITS / 4) / 256, 256>>>(out);
}

// round 14
// speedup vs baseline: 1.0516x; 1.0022x over previous
#include <cuda_runtime.h>
#include <cuda_fp16.h>
#include <math.h>
#include <stdint.h>

// ---------------------------------------------------------------------------
// ContinuousFilterConv, mma.sync fp16, persistent-A registers, h folded in fp16,
// pair-pipelined epochs (one wait/sync per 2 u).
//   C[e,i] = sum_u h[e,u] * (t @ W2'_u)[e,i]   (u=128 row: W2'=b2, h=1)
//   t fragments persistent in registers; per u: a_s = h*t (fp16x2 mul), MMA
//   accumulates directly into fp32 accC. B 4-slab cp.async ring, pair steps.
//   256 threads, 8 warps 4(M)x2(N), warp tile 32Mx64N -> ~195 regs.
// ---------------------------------------------------------------------------

#define N_NODES 20000
#define N_EDGES 8192
#define UNITS   128
#define NGAUSS  50
#define LDA     136            // padded row (fp16 elems) = 272 B

// ---- gmem scratch (static only) ----
__device__ __align__(16) float  g_hT[129 * N_EDGES];     // hT[u][e], row 128 == 1
__device__ __align__(16) __half g_th[N_EDGES * LDA];     // t fp16, padded rows
__device__ uint4 g_B4[129 * 2176];                       // W2'_u fp16, padded rows
__device__ __align__(16) float g_msg[N_NODES * UNITS];

// ---- helpers ----
__device__ __forceinline__ uint32_t smem_u32(const void* p) {
    uint32_t a;
    asm("{ .reg .u64 t; cvta.to.shared.u64 t, %1; cvt.u32.u64 %0, t; }" : "=r"(a) : "l"(p));
    return a;
}
__device__ __forceinline__ void cp16(uint32_t saddr, const void* g) {
    asm volatile("cp.async.cg.shared.global [%0], [%1], 16;" :: "r"(saddr), "l"(g) : "memory");
}
#define CP_COMMIT() asm volatile("cp.async.commit_group;" ::: "memory")
#define CP_WAIT0()  asm volatile("cp.async.wait_group 0;" ::: "memory")

#define LDSM4(R, A) \
    asm volatile("ldmatrix.sync.aligned.m8n8.x4.shared.b16 {%0,%1,%2,%3}, [%4];" \
        : "=r"((R)[0]), "=r"((R)[1]), "=r"((R)[2]), "=r"((R)[3]) : "r"(A))

#define MMA(C, A0, A1, A2, A3, B0, B1) \
    asm volatile("mma.sync.aligned.m16n8k16.row.col.f32.f16.f16.f32 " \
        "{%0,%1,%2,%3},{%4,%5,%6,%7},{%8,%9},{%0,%1,%2,%3};" \
        : "+f"((C)[0]), "+f"((C)[1]), "+f"((C)[2]), "+f"((C)[3]) \
        : "r"(A0), "r"(A1), "r"(A2), "r"(A3), "r"(B0), "r"(B1))

__device__ __forceinline__ uint32_t mulh2(uint32_t a, uint32_t h) {
    uint32_t r;
    asm("mul.rn.f16x2 %0, %1, %2;" : "=r"(r) : "r"(a), "r"(h));
    return r;
}
__device__ __forceinline__ uint32_t h2dup(float x) {
    uint32_t r;
    asm("{ .reg .f16 h; cvt.rn.f16.f32 h, %1; mov.b32 %0, {h, h}; }" : "=r"(r) : "f"(x));
    return r;
}
__device__ __forceinline__ uint32_t pack_h2(float x0, float x1) {
    return (uint32_t)__half_as_ushort(__float2half(x0))
         | ((uint32_t)__half_as_ushort(__float2half(x1)) << 16);
}
__device__ __forceinline__ float silu_f(float x) { return x / (1.0f + __expf(-x)); }

// ---------------------------------------------------------------------------
// kernel 1: W2/b2 -> fp16 padded rows + grid-stride zero of g_msg (fused)
// ---------------------------------------------------------------------------
__global__ __launch_bounds__(256) void w2_zero_kernel(
    const float* __restrict__ W2, const float* __restrict__ b2)
{
    int g  = blockIdx.x * 256 + threadIdx.x;       // < 129*2048
    int u  = g >> 11, rem = g & 2047;
    int i  = rem >> 4, jq = rem & 15;
    const float* row = (u < 128) ? (W2 + (long long)u * 16384) : b2;
    float4 a = *(const float4*)(row + i * 128 + jq * 8);
    float4 b = *(const float4*)(row + i * 128 + jq * 8 + 4);
    uint4 o;
    o.x = pack_h2(a.x, a.y);
    o.y = pack_h2(a.z, a.w);
    o.z = pack_h2(b.x, b.y);
    o.w = pack_h2(b.z, b.w);
    g_B4[u * 2176 + i * 17 + jq] = o;
    for (int k = g; k < N_NODES * UNITS / 4; k += 1032 * 256)
        ((float4*)g_msg)[k] = make_float4(0.f, 0.f, 0.f, 0.f);
}

// ---------------------------------------------------------------------------
// kernel 2: per-edge h (gaussian -> dense -> silu, transposed) + t (gather @ Wt)
// ---------------------------------------------------------------------------
__global__ __launch_bounds__(256) void prep_kernel(
    const float* __restrict__ nf, const int* __restrict__ eidx,
    const float* __restrict__ dist, const float* __restrict__ W1,
    const float* __restrict__ b1, const float* __restrict__ Wt)
{
    extern __shared__ float sm[];
    float* Wt_s = sm;                       // 16384
    float* W1_s = Wt_s + 16384;             // 6400
    float* b1_s = W1_s + 6400;              // 128
    float* X_s  = b1_s + 128;               // 64*129
    float* df_s = X_s + 64 * 129;           // 64*51
    const int tid = threadIdx.x;
    const int e0  = blockIdx.x * 64;

    for (int idx = tid; idx < 16384; idx += 256) Wt_s[idx] = Wt[idx];
    for (int idx = tid; idx < NGAUSS * UNITS; idx += 256) W1_s[idx] = W1[idx];
    if (tid < 128) b1_s[tid] = b1[tid];
    for (int idx = tid; idx < 64 * NGAUSS; idx += 256) {
        int e = idx & 63, g = idx >> 6;
        float d = dist[e0 + e];
        float c = (30.0f / 49.0f) * (float)g;
        float x = d - c;
        df_s[e * 51 + g] = __expf(-10.0f * x * x);
    }
    for (int idx = tid; idx < 64 * UNITS; idx += 256) {
        int e = idx >> 7, j = idx & 127;
        int s = eidx[e0 + e];
        X_s[e * 129 + j] = nf[(long long)s * UNITS + j];
    }
    __syncthreads();

    for (int o = tid; o < 64 * UNITS; o += 256) {
        int u = o >> 6, e = o & 63;
        float acc = b1_s[u];
        const float* dfr = df_s + e * 51;
#pragma unroll
        for (int g = 0; g < NGAUSS; ++g) acc += dfr[g] * W1_s[g * UNITS + u];
        g_hT[u * N_EDGES + e0 + e] = silu_f(acc);
    }
    for (int idx = tid; idx < 64; idx += 256)
        g_hT[128 * N_EDGES + e0 + idx] = 1.0f;

    for (int o = tid; o < 64 * UNITS; o += 256) {
        int e = o >> 7, u = o & 127;
        float acc = 0.0f;
        const float* xr = X_s + e * 129;
#pragma unroll
        for (int j = 0; j < UNITS; ++j) acc += xr[j] * Wt_s[j * UNITS + u];
        g_th[(e0 + e) * LDA + u] = __float2half(acc);
    }
}

// ---------------------------------------------------------------------------
// kernel 3: main GEMM, persistent-A, pair epochs.
// 256 threads (8 warps, 4Mx2N of 32x64); B 4-slab ring, t in dedicated staging.
// ---------------------------------------------------------------------------
#define HS_OFF 0
#define TST_OFF 33280
#define B_OFF  68096
#define BBUF   34816
#define CONV_SMEM 207360   // 68096 + 4*34816

__global__ __launch_bounds__(256, 1) void conv_kernel(
    const int* __restrict__ eidx, const float* __restrict__ dist)
{
    extern __shared__ char smem[];
    const uint32_t sb = smem_u32(smem);
    const int tid = threadIdx.x, l = tid & 31, wid = tid >> 5;
    const int e0 = blockIdx.x * 128;
    const int ub = blockIdx.y ? 65 : 0;
    const int ue = blockIdx.y ? 129 : 65;
    const int nu = ue - ub;                 // 65 or 64
    const int np = nu >> 1;
    const int tail = nu & 1;

    // G0: B[ub]->slab0, B[ub+1]->slab1, t->TST, h->HS
    {
        const uint4* gb = g_B4 + ub * 2176;
        for (int k = tid; k < 2 * 2176; k += 256) cp16(sb + B_OFF + k * 16, gb + k);
        const uint4* gt = (const uint4*)(g_th + (long long)e0 * LDA);
        for (int k = tid; k < 2176; k += 256) cp16(sb + TST_OFF + k * 16, gt + k);
        for (int k = tid; k < nu * 32; k += 256) {
            int u_l = k >> 5, off = k & 31;
            cp16(sb + HS_OFF + k * 16,
                 (const uint4*)(g_hT + (ub + u_l) * N_EDGES + e0) + off);
        }
        CP_COMMIT();
    }

    const int m0w = (wid & 3) * 32;         // 4 M groups of 32 rows
    const int n0w = (wid >> 2) * 64;        // 2 N groups of 64 cols
    const uint32_t aOff = (uint32_t)(m0w + (l & 7) + ((l >> 3) & 1) * 8) * (LDA * 2)
                        + (uint32_t)(l >> 4) * 16;
    const uint32_t bOff = (uint32_t)(n0w + (l & 7) + ((l >> 4) & 1) * 8) * (LDA * 2)
                        + (uint32_t)((l >> 3) & 1) * 16;
    const float* hbase = (const float*)(smem + HS_OFF);
    const int hr = (l >> 2);                // fragment row within 16-tile

    CP_WAIT0();            // G0 done: B0, B1, t, h ready
    __syncthreads();

    // persistent A fragments from t staging
    uint32_t ap[2][8][4];
#pragma unroll
    for (int mt = 0; mt < 2; ++mt)
#pragma unroll
        for (int kc = 0; kc < 8; ++kc)
            LDSM4(ap[mt][kc], sb + TST_OFF + aOff
                              + (uint32_t)mt * 16 * (LDA * 2) + (uint32_t)kc * 32);

    float accC[2][8][4];
#pragma unroll
    for (int mt = 0; mt < 2; ++mt)
#pragma unroll
        for (int nt = 0; nt < 8; ++nt)
#pragma unroll
            for (int q = 0; q < 4; ++q) accC[mt][nt][q] = 0.0f;

    for (int p = 0; p < np; ++p) {
        const int k0 = 2 * p;
        if (p > 0) {       // pair p's B committed at p-1; wait + guard slab reuse
            CP_WAIT0();
            __syncthreads();
        }
        // prefetch pair p+1 into the other two slabs; one commit per iter
        {
            int ka = k0 + 2, kb = k0 + 3;
            if (ka < nu) {
                const uint4* gb = g_B4 + (ub + ka) * 2176;
                uint32_t dst = sb + B_OFF + (uint32_t)(ka & 3) * BBUF;
                for (int kk = tid; kk < 2176; kk += 256) cp16(dst + kk * 16, gb + kk);
            }
            if (kb < nu) {
                const uint4* gb = g_B4 + (ub + kb) * 2176;
                uint32_t dst = sb + B_OFF + (uint32_t)(kb & 3) * BBUF;
                for (int kk = tid; kk < 2176; kk += 256) cp16(dst + kk * 16, gb + kk);
            }
            CP_COMMIT();
        }

        // h scales for the two u of this pair
        const float* hrow0 = hbase + k0 * 128;
        const float* hrow1 = hrow0 + 128;
        uint32_t h00 = h2dup(hrow0[m0w + hr]);
        uint32_t h01 = h2dup(hrow0[m0w + hr + 8]);
        uint32_t h10 = h2dup(hrow0[m0w + 16 + hr]);
        uint32_t h11 = h2dup(hrow0[m0w + 16 + hr + 8]);
        uint32_t g00 = h2dup(hrow1[m0w + hr]);
        uint32_t g01 = h2dup(hrow1[m0w + hr + 8]);
        uint32_t g10 = h2dup(hrow1[m0w + 16 + hr]);
        uint32_t g11 = h2dup(hrow1[m0w + 16 + hr + 8]);

        const uint32_t b0Base = sb + B_OFF + (uint32_t)(k0 & 3) * BBUF + bOff;
        const uint32_t b1Base = sb + B_OFF + (uint32_t)((k0 + 1) & 3) * BBUF + bOff;

#pragma unroll
        for (int kc = 0; kc < 8; ++kc) {
            uint32_t bf0[4][4], bf1[4][4];
#pragma unroll
            for (int bt = 0; bt < 4; ++bt) {
                LDSM4(bf0[bt], b0Base + (uint32_t)bt * 16 * (LDA * 2) + (uint32_t)kc * 32);
                LDSM4(bf1[bt], b1Base + (uint32_t)bt * 16 * (LDA * 2) + (uint32_t)kc * 32);
            }
            uint32_t as[4];
            // u0, mt0
            as[0] = mulh2(ap[0][kc][0], h00); as[1] = mulh2(ap[0][kc][1], h01);
            as[2] = mulh2(ap[0][kc][2], h00); as[3] = mulh2(ap[0][kc][3], h01);
#pragma unroll
            for (int nt = 0; nt < 8; ++nt)
                MMA(accC[0][nt], as[0], as[1], as[2], as[3],
                    bf0[nt >> 1][(nt & 1) * 2], bf0[nt >> 1][(nt & 1) * 2 + 1]);
            // u0, mt1
            as[0] = mulh2(ap[1][kc][0], h10); as[1] = mulh2(ap[1][kc][1], h11);
            as[2] = mulh2(ap[1][kc][2], h10); as[3] = mulh2(ap[1][kc][3], h11);
#pragma unroll
            for (int nt = 0; nt < 8; ++nt)
                MMA(accC[1][nt], as[0], as[1], as[2], as[3],
                    bf0[nt >> 1][(nt & 1) * 2], bf0[nt >> 1][(nt & 1) * 2 + 1]);
            // u1, mt0
            as[0] = mulh2(ap[0][kc][0], g00); as[1] = mulh2(ap[0][kc][1], g01);
            as[2] = mulh2(ap[0][kc][2], g00); as[3] = mulh2(ap[0][kc][3], g01);
#pragma unroll
            for (int nt = 0; nt < 8; ++nt)
                MMA(accC[0][nt], as[0], as[1], as[2], as[3],
                    bf1[nt >> 1][(nt & 1) * 2], bf1[nt >> 1][(nt & 1) * 2 + 1]);
            // u1, mt1
            as[0] = mulh2(ap[1][kc][0], g10); as[1] = mulh2(ap[1][kc][1], g11);
            as[2] = mulh2(ap[1][kc][2], g10); as[3] = mulh2(ap[1][kc][3], g11);
#pragma unroll
            for (int nt = 0; nt < 8; ++nt)
                MMA(accC[1][nt], as[0], as[1], as[2], as[3],
                    bf1[nt >> 1][(nt & 1) * 2], bf1[nt >> 1][(nt & 1) * 2 + 1]);
        }
    }

    if (tail) {            // last odd u (k = nu-1), B loaded by p=np-1 prefetch
        const int k0 = nu - 1;
        CP_WAIT0();
        __syncthreads();
        const float* hrow0 = hbase + k0 * 128;
        uint32_t h00 = h2dup(hrow0[m0w + hr]);
        uint32_t h01 = h2dup(hrow0[m0w + hr + 8]);
        uint32_t h10 = h2dup(hrow0[m0w + 16 + hr]);
        uint32_t h11 = h2dup(hrow0[m0w + 16 + hr + 8]);
        const uint32_t b0Base = sb + B_OFF + (uint32_t)(k0 & 3) * BBUF + bOff;
#pragma unroll
        for (int kc = 0; kc < 8; ++kc) {
            uint32_t bf0[4][4];
#pragma unroll
            for (int bt = 0; bt < 4; ++bt)
                LDSM4(bf0[bt], b0Base + (uint32_t)bt * 16 * (LDA * 2) + (uint32_t)kc * 32);
            uint32_t as[4];
            as[0] = mulh2(ap[0][kc][0], h00); as[1] = mulh2(ap[0][kc][1], h01);
            as[2] = mulh2(ap[0][kc][2], h00); as[3] = mulh2(ap[0][kc][3], h01);
#pragma unroll
            for (int nt = 0; nt < 8; ++nt)
                MMA(accC[0][nt], as[0], as[1], as[2], as[3],
                    bf0[nt >> 1][(nt & 1) * 2], bf0[nt >> 1][(nt & 1) * 2 + 1]);
            as[0] = mulh2(ap[1][kc][0], h10); as[1] = mulh2(ap[1][kc][1], h11);
            as[2] = mulh2(ap[1][kc][2], h10); as[3] = mulh2(ap[1][kc][3], h11);
#pragma unroll
            for (int nt = 0; nt < 8; ++nt)
                MMA(accC[1][nt], as[0], as[1], as[2], as[3],
                    bf0[nt >> 1][(nt & 1) * 2], bf0[nt >> 1][(nt & 1) * 2 + 1]);
        }
    }

    // epilogue: cutoff mask + scatter-add
#pragma unroll
    for (int mt = 0; mt < 2; ++mt) {
        int e1 = e0 + m0w + mt * 16 + hr;
        int e2 = e1 + 8;
        float d1 = dist[e1], d2 = dist[e2];
        bool ok1 = (d1 <= 8.0f), ok2 = (d2 <= 8.0f);
        float* r1 = g_msg + (long long)eidx[N_EDGES + e1] * UNITS;
        float* r2 = g_msg + (long long)eidx[N_EDGES + e2] * UNITS;
#pragma unroll
        for (int nt = 0; nt < 8; ++nt) {
            int n = n0w + nt * 8 + (l & 3) * 2;
            if (ok1) {
                atomicAdd(r1 + n,     accC[mt][nt][0]);
                atomicAdd(r1 + n + 1, accC[mt][nt][1]);
            }
            if (ok2) {
                atomicAdd(r2 + n,     accC[mt][nt][2]);
                atomicAdd(r2 + n + 1, accC[mt][nt][3]);
            }
        }
    }
}

// ---------------------------------------------------------------------------
// kernel 4: out = silu(messages), float4
// ---------------------------------------------------------------------------
__global__ void out_kernel(float* __restrict__ out) {
    int i = blockIdx.x * blockDim.x + threadIdx.x;  // grid sized exactly (160000)
    float4 x = ((const float4*)g_msg)[i];
    float4 y;
    y.x = silu_f(x.x); y.y = silu_f(x.y); y.z = silu_f(x.z); y.w = silu_f(x.w);
    ((float4*)out)[i] = y;
}

// ---------------------------------------------------------------------------
extern "C" void kernel_launch(void* const* d_in, const int* in_sizes, int n_in,
                              void* d_out, int out_size) {
    const float* nf   = (const float*)d_in[0];
    const int*   eidx = (const int*)  d_in[1];
    const float* dist = (const float*)d_in[2];
    const float* W1   = (const float*)d_in[3];
    const float* b1   = (const float*)d_in[4];
    const float* W2   = (const float*)d_in[5];
    const float* b2   = (const float*)d_in[6];
    const float* Wt   = (const float*)d_in[7];
    float* out = (float*)d_out;

    const int PREP_SMEM = (16384 + 6400 + 128 + 64 * 129 + 64 * 51) * 4;
    cudaFuncSetAttribute(prep_kernel, cudaFuncAttributeMaxDynamicSharedMemorySize, PREP_SMEM);
    cudaFuncSetAttribute(conv_kernel, cudaFuncAttributeMaxDynamicSharedMemorySize, CONV_SMEM);

    w2_zero_kernel<<<129 * 2048 / 256, 256>>>(W2, b2);
    prep_kernel<<<N_EDGES / 64, 256, PREP_SMEM>>>(nf, eidx, dist, W1, b1, Wt);
    conv_kernel<<<dim3(N_EDGES / 128, 2), 256, CONV_SMEM>>>(eidx, dist);
    out_kernel<<<(N_NODES * UNITS / 4) / 256, 256>>>(out);
}